// round 15
// baseline (speedup 1.0000x reference)
#include <cuda_runtime.h>
#include <cuda_fp16.h>
#include <math.h>

// ---------------------------------------------------------------------------
// Encoder_conv2: 5-level grid encoder, two kernels.
//  k_prep (18 blocks, level+slice fully templated, conv sliced to the rows
//    the node slice needs): conv3x3+tanh -> smem -> merged half-int-lattice
//    nodes -> packed fp16 parity-pair copies -> g_G (gmem, 125 KB).
//  k_sample (148 blocks): copy g_G -> smem; per-warp DYNAMIC queue over
//    128-pt claims; (point,level)-per-thread-slot mapping -> coalesced
//    STG.128 straight from registers; coords via one coalesced load per
//    window + SHFL.IDX per slot.
// Pair layout per level: copy A = texel pairs (2j,2j+1), copy B = (2j+1,2j+2);
// corners (m0,m0+1) are one 16B chunk at (m0&1 ? B : A) + k*rowb + (m0&~1)*8.
// Values scaled by 2^10 into fp16; 2^-10 folded exactly into blend weights.
// ---------------------------------------------------------------------------

#define GBT   125184       // sum (2r)^2 * 16 bytes (2 copies x 8B texel)

#define SCALE_UP 1024.0f
#define SCALE_DN (1.0f / 1024.0f)

#define LB_(l)   ((l)==0?0:(l)==1?4096:(l)==2?13312:(l)==3?38912:59648)

__device__ uint2 g_G[GBT / 8];   // packed grids, built by k_prep
__device__ int   g_cursor = 0;   // sampler work queue (128-pt claims)
__device__ int   g_wdone  = 0;   // warps finished (for reset)

// ---------------------------------------------------------------------------
// k_prep: 18 blocks; (level, slice) fully compile-time. Conv computed only
// for rows [YLO,YHI] that this node slice reads.
// ---------------------------------------------------------------------------
template<int V, int W_> struct MinI { static const int v = V < W_ ? V : W_; };

template<int R, int LB, int SLICES, int SLICE>
__device__ __forceinline__ void prep_level(const float* __restrict__ F,
                                           const float* w, float4* sa, int tid) {
    constexpr int N2   = 2 * R;
    constexpr int ROWS = N2 / SLICES;          // node rows in this slice
    constexpr int K0   = SLICE * ROWS;
    constexpr int YLO  = K0 / 2;
    constexpr int YHI  = MinI<R - 1, (K0 + ROWS) / 2 + 1>::v;
    constexpr int NR   = YHI - YLO + 1;        // conv rows needed

    // conv3x3 (SAME, zero pad, cross-correlation) + tanh for rows [YLO,YHI]
    #pragma unroll 1
    for (int tex = tid; tex < 2 * NR * R; tex += 1024) {
        int j    = tex / (NR * R);
        int rem  = tex - j * (NR * R);
        int yloc = rem / R;
        int x    = rem - yloc * R;
        int y    = YLO + yloc;

        float oc[4];
        #pragma unroll
        for (int c = 0; c < 4; c++) {
            float s = 0.f;
            #pragma unroll
            for (int dy = 0; dy < 3; dy++) {
                int yy = y + dy - 1;
                if (yy < 0 || yy >= R) continue;
                #pragma unroll
                for (int dx = 0; dx < 3; dx++) {
                    int xx = x + dx - 1;
                    if (xx < 0 || xx >= R) continue;
                    s += __ldg(&F[((j * 4 + c) * R + yy) * R + xx]) * w[c * 9 + dy * 3 + dx];
                }
            }
            oc[c] = tanhf(s);
        }
        sa[j * NR * R + yloc * R + x] = make_float4(oc[0], oc[1], oc[2], oc[3]);
    }
    __syncthreads();

    // this slice's node rows -> packed fp16 parity-pair copies (gmem)
    uint2* lb = g_G + LB / 8;
    #pragma unroll 1
    for (int tex = tid; tex < ROWS * N2; tex += 1024) {
        int k = K0 + tex / N2;
        int m = tex - (tex / N2) * N2;

        float ax = 0.f, ay = 0.f, az = 0.f, aw = 0.f;
        #pragma unroll
        for (int j = 0; j < 2; j++) {
            float px = 0.5f * (float)(m + j);
            float py = 0.5f * (float)(k + j);
            float fx = floorf(px), fy = floorf(py);
            float wx = px - fx,    wy = py - fy;
            int ix0 = (int)fx, iy0 = (int)fy;
            int x0 = min(max(ix0,     0), R - 1);
            int x1 = min(max(ix0 + 1, 0), R - 1);
            int y0 = min(max(iy0,     0), R - 1);
            int y1 = min(max(iy0 + 1, 0), R - 1);
            int base = j * NR * R - YLO * R;       // sa is row-rebased by YLO
            float4 c00 = sa[base + y0 * R + x0];
            float4 c01 = sa[base + y0 * R + x1];
            float4 c10 = sa[base + y1 * R + x0];
            float4 c11 = sa[base + y1 * R + x1];
            float w00 = (1.f - wx) * (1.f - wy);
            float w01 = wx * (1.f - wy);
            float w10 = (1.f - wx) * wy;
            float w11 = wx * wy;
            ax += c00.x * w00 + c01.x * w01 + c10.x * w10 + c11.x * w11;
            ay += c00.y * w00 + c01.y * w01 + c10.y * w10 + c11.y * w11;
            az += c00.z * w00 + c01.z * w01 + c10.z * w10 + c11.z * w11;
            aw += c00.w * w00 + c01.w * w01 + c10.w * w10 + c11.w * w11;
        }
        __half2 h01 = __floats2half2_rn(ax * SCALE_UP, ay * SCALE_UP);
        __half2 h23 = __floats2half2_rn(az * SCALE_UP, aw * SCALE_UP);
        uint2 val;
        val.x = *reinterpret_cast<unsigned int*>(&h01);
        val.y = *reinterpret_cast<unsigned int*>(&h23);

        lb[k * N2 + m] = val;                                  // copy A
        if (m >= 1) lb[N2 * N2 + k * N2 + (m - 1)] = val;      // copy B
    }
}

__global__ void __launch_bounds__(1024, 1)
k_prep(const float* __restrict__ F0, const float* __restrict__ F1,
       const float* __restrict__ F2, const float* __restrict__ F3,
       const float* __restrict__ F4, const float* __restrict__ W) {
    __shared__ float4 sa[512];
    const int tid = threadIdx.x;

    float w[36];
    #pragma unroll
    for (int i = 0; i < 36; i++) w[i] = W[i];

    switch (blockIdx.x) {
        case 0:  prep_level< 8, LB_(0), 1, 0>(F0, w, sa, tid); break;
        case 1:  prep_level<12, LB_(1), 1, 0>(F1, w, sa, tid); break;
        case 2:  prep_level<20, LB_(2), 4, 0>(F2, w, sa, tid); break;
        case 3:  prep_level<20, LB_(2), 4, 1>(F2, w, sa, tid); break;
        case 4:  prep_level<20, LB_(2), 4, 2>(F2, w, sa, tid); break;
        case 5:  prep_level<20, LB_(2), 4, 3>(F2, w, sa, tid); break;
        case 6:  prep_level<18, LB_(3), 4, 0>(F3, w, sa, tid); break;
        case 7:  prep_level<18, LB_(3), 4, 1>(F3, w, sa, tid); break;
        case 8:  prep_level<18, LB_(3), 4, 2>(F3, w, sa, tid); break;
        case 9:  prep_level<18, LB_(3), 4, 3>(F3, w, sa, tid); break;
        case 10: prep_level<32, LB_(4), 8, 0>(F4, w, sa, tid); break;
        case 11: prep_level<32, LB_(4), 8, 1>(F4, w, sa, tid); break;
        case 12: prep_level<32, LB_(4), 8, 2>(F4, w, sa, tid); break;
        case 13: prep_level<32, LB_(4), 8, 3>(F4, w, sa, tid); break;
        case 14: prep_level<32, LB_(4), 8, 4>(F4, w, sa, tid); break;
        case 15: prep_level<32, LB_(4), 8, 5>(F4, w, sa, tid); break;
        case 16: prep_level<32, LB_(4), 8, 6>(F4, w, sa, tid); break;
        default: prep_level<32, LB_(4), 8, 7>(F4, w, sa, tid); break;
    }
}

// ---------------------------------------------------------------------------
// k_sample: smem = packed grids only (125184 B). Per-warp dynamic queue.
// ---------------------------------------------------------------------------
#define NTHR 1024
#define CLAIM_WIN 4      // 4 x 32-pt windows = 128 pts per atomic claim

__global__ void __launch_bounds__(NTHR, 1)
k_sample(const float* __restrict__ X, const float* __restrict__ Y,
         float* __restrict__ out, int npts) {
    extern __shared__ unsigned char smraw[];
    const int tid = threadIdx.x;

    // coalesced copy of packed grids: 7824 uint4
    {
        const uint4* src = reinterpret_cast<const uint4*>(g_G);
        uint4* dst = reinterpret_cast<uint4*>(smraw);
        for (int i = tid; i < GBT / 16; i += NTHR) dst[i] = src[i];
    }
    __syncthreads();

    const int lane = tid & 31;

    // loop-invariant per-slot state: q = (s*32+lane)/5, level consts packed
    int      qoff_[5];
    float    sx_[5];
    unsigned lr_[5];          // lbase | (rowb << 16);  asize = rowb*rowb/8
    #pragma unroll
    for (int s = 0; s < 5; s++) {
        int j = s * 32 + lane;
        int q = j / 5;
        int l = j - q * 5;
        qoff_[s] = q;
        int n2 = (l == 0) ? 16 : (l == 1) ? 24 : (l == 2) ? 40 : (l == 3) ? 36 : 64;
        unsigned lbase = (l == 0) ? 0u : (l == 1) ? 4096u : (l == 2) ? 13312u
                       : (l == 3) ? 38912u : 59648u;
        sx_[s] = (float)(n2 - 2);
        lr_[s] = lbase | ((unsigned)(n2 * 8) << 16);
    }

    float4* og = reinterpret_cast<float4*>(out);

    while (true) {
        int c = 0;
        if (lane == 0) c = atomicAdd(&g_cursor, 1);
        c = __shfl_sync(0xffffffffu, c, 0);
        int base = c * (CLAIM_WIN * 32);
        if (base >= npts) break;

        #pragma unroll 1
        for (int u = 0; u < CLAIM_WIN; u++) {
            int wb = base + u * 32;
            if (wb >= npts) break;

            int pl = wb + lane;
            float xv = (pl < npts) ? __ldg(&X[pl]) : 0.f;   // coalesced
            float yv = (pl < npts) ? __ldg(&Y[pl]) : 0.f;
            size_t ob = (size_t)wb * 5 + lane;              // store base (float4)

            #pragma unroll
            for (int s = 0; s < 5; s++) {
                int q = qoff_[s];
                int p = wb + q;
                float hx = __shfl_sync(0xffffffffu, xv, q);
                float hy = __shfl_sync(0xffffffffu, yv, q);
                if (p < npts) {
                    unsigned lr    = lr_[s];
                    unsigned lbase = lr & 0xFFFFu;
                    unsigned rowb  = lr >> 16;
                    unsigned asize = (rowb * rowb) >> 3;    // n2*n2*8
                    float sx = sx_[s];

                    float h = hx * sx;
                    float v = hy * sx;
                    float fm = floorf(h), fk = floorf(v);
                    int m0 = (int)fm, k0 = (int)fk;         // in-range, no clamps
                    float wx = h - fm, wy = v - fk;

                    unsigned addr = lbase + (unsigned)(m0 & 1) * asize
                                  + (unsigned)k0 * rowb + (unsigned)(m0 & ~1) * 8u;
                    uint4 t0 = *reinterpret_cast<const uint4*>(smraw + addr);         // c00,c01
                    uint4 t1 = *reinterpret_cast<const uint4*>(smraw + addr + rowb);  // c10,c11

                    float2 a00 = __half22float2(*reinterpret_cast<__half2*>(&t0.x));
                    float2 b00 = __half22float2(*reinterpret_cast<__half2*>(&t0.y));
                    float2 a01 = __half22float2(*reinterpret_cast<__half2*>(&t0.z));
                    float2 b01 = __half22float2(*reinterpret_cast<__half2*>(&t0.w));
                    float2 a10 = __half22float2(*reinterpret_cast<__half2*>(&t1.x));
                    float2 b10 = __half22float2(*reinterpret_cast<__half2*>(&t1.y));
                    float2 a11 = __half22float2(*reinterpret_cast<__half2*>(&t1.z));
                    float2 b11 = __half22float2(*reinterpret_cast<__half2*>(&t1.w));

                    float wyS = wy * SCALE_DN;
                    float wyB = SCALE_DN - wyS;             // (1-wy)*2^-10 exactly
                    float wxb = 1.f - wx;
                    float w00 = wxb * wyB;
                    float w01 = wx  * wyB;
                    float w10 = wxb * wyS;
                    float w11 = wx  * wyS;

                    float4 o;
                    o.x = a00.x * w00 + a01.x * w01 + a10.x * w10 + a11.x * w11;
                    o.y = a00.y * w00 + a01.y * w01 + a10.y * w10 + a11.y * w11;
                    o.z = b00.x * w00 + b01.x * w01 + b10.x * w10 + b11.x * w11;
                    o.w = b00.y * w00 + b01.y * w01 + b10.y * w10 + b11.y * w11;

                    og[ob + s * 32] = o;                    // fully coalesced STG.128
                }
            }
        }
    }

    // last-exiting warp resets the queue for the next launch / graph replay.
    // Safe: a warp bumps g_wdone only after its final cursor op, so when the
    // last warp sees the full count, no further cursor accesses exist.
    if (lane == 0) {
        __threadfence();
        int total = (int)gridDim.x * (NTHR / 32);
        int d = atomicAdd(&g_wdone, 1);
        if (d == total - 1) {
            g_cursor = 0;
            g_wdone  = 0;
            __threadfence();
        }
    }
}

// ---------------------------------------------------------------------------
extern "C" void kernel_launch(void* const* d_in, const int* in_sizes, int n_in,
                              void* d_out, int out_size) {
    const float* X = nullptr;
    const float* Yv = nullptr;
    const float* W = nullptr;
    const float* F[5] = {nullptr, nullptr, nullptr, nullptr, nullptr};
    int npts = 0;

    for (int i = 0; i < n_in; i++) {
        int s = in_sizes[i];
        const float* p = (const float*)d_in[i];
        if (s == 36)        W    = p;
        else if (s == 512)  F[0] = p;
        else if (s == 1152) F[1] = p;
        else if (s == 3200) F[2] = p;
        else if (s == 2592) F[3] = p;
        else if (s == 8192) F[4] = p;
        else {
            if (!X) { X = p; npts = s; }
            else     Yv = p;
        }
    }

    static int nsm = 0;
    static bool init_done = false;
    if (!init_done) {
        cudaFuncSetAttribute(k_sample, cudaFuncAttributeMaxDynamicSharedMemorySize, GBT);
        cudaDeviceGetAttribute(&nsm, cudaDevAttrMultiProcessorCount, 0);
        if (nsm <= 0) nsm = 148;
        init_done = true;
    }

    k_prep<<<18, 1024>>>(F[0], F[1], F[2], F[3], F[4], W);
    k_sample<<<nsm, NTHR, GBT>>>(X, Yv, (float*)d_out, npts);
}

// round 16
// speedup vs baseline: 1.1158x; 1.1158x over previous
#include <cuda_runtime.h>
#include <cuda_fp16.h>
#include <math.h>

// ---------------------------------------------------------------------------
// Encoder_conv2: 5-level grid encoder, two kernels.
//  k_prep (18 blocks, level+slice fully templated, conv sliced to the rows
//    the node slice needs): conv3x3+tanh -> smem -> merged half-int-lattice
//    nodes -> packed fp16 parity-pair copies -> g_G (gmem, 125 KB).
//  k_sample (148 blocks, R14-proven): copy g_G -> smem; static grid-stride;
//    (point,level)-per-thread-slot mapping -> coalesced STG.128 straight from
//    registers; per-slot loop-invariant constants in registers.
// Pair layout per level: copy A = texel pairs (2j,2j+1), copy B = (2j+1,2j+2);
// corners (m0,m0+1) are one 16B chunk at (m0&1 ? B : A) + k*rowb + (m0&~1)*8.
// Values scaled by 2^10 into fp16; 2^-10 folded exactly into blend weights.
// ---------------------------------------------------------------------------

#define GBT   125184       // sum (2r)^2 * 16 bytes (2 copies x 8B texel)

#define SCALE_UP 1024.0f
#define SCALE_DN (1.0f / 1024.0f)

#define LB_(l)   ((l)==0?0:(l)==1?4096:(l)==2?13312:(l)==3?38912:59648)

__device__ uint2 g_G[GBT / 8];   // packed grids, built by k_prep

// ---------------------------------------------------------------------------
// k_prep: 18 blocks; (level, slice) fully compile-time. Conv computed only
// for rows [YLO,YHI] that this node slice reads.
// ---------------------------------------------------------------------------
template<int V, int W_> struct MinI { static const int v = V < W_ ? V : W_; };

template<int R, int LB, int SLICES, int SLICE>
__device__ __forceinline__ void prep_level(const float* __restrict__ F,
                                           const float* w, float4* sa, int tid) {
    constexpr int N2   = 2 * R;
    constexpr int ROWS = N2 / SLICES;          // node rows in this slice
    constexpr int K0   = SLICE * ROWS;
    constexpr int YLO  = K0 / 2;
    constexpr int YHI  = MinI<R - 1, (K0 + ROWS) / 2 + 1>::v;
    constexpr int NR   = YHI - YLO + 1;        // conv rows needed

    // conv3x3 (SAME, zero pad, cross-correlation) + tanh for rows [YLO,YHI]
    #pragma unroll 1
    for (int tex = tid; tex < 2 * NR * R; tex += 1024) {
        int j    = tex / (NR * R);
        int rem  = tex - j * (NR * R);
        int yloc = rem / R;
        int x    = rem - yloc * R;
        int y    = YLO + yloc;

        float oc[4];
        #pragma unroll
        for (int c = 0; c < 4; c++) {
            float s = 0.f;
            #pragma unroll
            for (int dy = 0; dy < 3; dy++) {
                int yy = y + dy - 1;
                if (yy < 0 || yy >= R) continue;
                #pragma unroll
                for (int dx = 0; dx < 3; dx++) {
                    int xx = x + dx - 1;
                    if (xx < 0 || xx >= R) continue;
                    s += __ldg(&F[((j * 4 + c) * R + yy) * R + xx]) * w[c * 9 + dy * 3 + dx];
                }
            }
            oc[c] = tanhf(s);
        }
        sa[j * NR * R + yloc * R + x] = make_float4(oc[0], oc[1], oc[2], oc[3]);
    }
    __syncthreads();

    // this slice's node rows -> packed fp16 parity-pair copies (gmem)
    uint2* lb = g_G + LB / 8;
    #pragma unroll 1
    for (int tex = tid; tex < ROWS * N2; tex += 1024) {
        int k = K0 + tex / N2;
        int m = tex - (tex / N2) * N2;

        float ax = 0.f, ay = 0.f, az = 0.f, aw = 0.f;
        #pragma unroll
        for (int j = 0; j < 2; j++) {
            float px = 0.5f * (float)(m + j);
            float py = 0.5f * (float)(k + j);
            float fx = floorf(px), fy = floorf(py);
            float wx = px - fx,    wy = py - fy;
            int ix0 = (int)fx, iy0 = (int)fy;
            int x0 = min(max(ix0,     0), R - 1);
            int x1 = min(max(ix0 + 1, 0), R - 1);
            int y0 = min(max(iy0,     0), R - 1);
            int y1 = min(max(iy0 + 1, 0), R - 1);
            int base = j * NR * R - YLO * R;       // sa is row-rebased by YLO
            float4 c00 = sa[base + y0 * R + x0];
            float4 c01 = sa[base + y0 * R + x1];
            float4 c10 = sa[base + y1 * R + x0];
            float4 c11 = sa[base + y1 * R + x1];
            float w00 = (1.f - wx) * (1.f - wy);
            float w01 = wx * (1.f - wy);
            float w10 = (1.f - wx) * wy;
            float w11 = wx * wy;
            ax += c00.x * w00 + c01.x * w01 + c10.x * w10 + c11.x * w11;
            ay += c00.y * w00 + c01.y * w01 + c10.y * w10 + c11.y * w11;
            az += c00.z * w00 + c01.z * w01 + c10.z * w10 + c11.z * w11;
            aw += c00.w * w00 + c01.w * w01 + c10.w * w10 + c11.w * w11;
        }
        __half2 h01 = __floats2half2_rn(ax * SCALE_UP, ay * SCALE_UP);
        __half2 h23 = __floats2half2_rn(az * SCALE_UP, aw * SCALE_UP);
        uint2 val;
        val.x = *reinterpret_cast<unsigned int*>(&h01);
        val.y = *reinterpret_cast<unsigned int*>(&h23);

        lb[k * N2 + m] = val;                                  // copy A
        if (m >= 1) lb[N2 * N2 + k * N2 + (m - 1)] = val;      // copy B
    }
}

__global__ void __launch_bounds__(1024, 1)
k_prep(const float* __restrict__ F0, const float* __restrict__ F1,
       const float* __restrict__ F2, const float* __restrict__ F3,
       const float* __restrict__ F4, const float* __restrict__ W) {
    __shared__ float4 sa[512];
    const int tid = threadIdx.x;

    float w[36];
    #pragma unroll
    for (int i = 0; i < 36; i++) w[i] = W[i];

    switch (blockIdx.x) {
        case 0:  prep_level< 8, LB_(0), 1, 0>(F0, w, sa, tid); break;
        case 1:  prep_level<12, LB_(1), 1, 0>(F1, w, sa, tid); break;
        case 2:  prep_level<20, LB_(2), 4, 0>(F2, w, sa, tid); break;
        case 3:  prep_level<20, LB_(2), 4, 1>(F2, w, sa, tid); break;
        case 4:  prep_level<20, LB_(2), 4, 2>(F2, w, sa, tid); break;
        case 5:  prep_level<20, LB_(2), 4, 3>(F2, w, sa, tid); break;
        case 6:  prep_level<18, LB_(3), 4, 0>(F3, w, sa, tid); break;
        case 7:  prep_level<18, LB_(3), 4, 1>(F3, w, sa, tid); break;
        case 8:  prep_level<18, LB_(3), 4, 2>(F3, w, sa, tid); break;
        case 9:  prep_level<18, LB_(3), 4, 3>(F3, w, sa, tid); break;
        case 10: prep_level<32, LB_(4), 8, 0>(F4, w, sa, tid); break;
        case 11: prep_level<32, LB_(4), 8, 1>(F4, w, sa, tid); break;
        case 12: prep_level<32, LB_(4), 8, 2>(F4, w, sa, tid); break;
        case 13: prep_level<32, LB_(4), 8, 3>(F4, w, sa, tid); break;
        case 14: prep_level<32, LB_(4), 8, 4>(F4, w, sa, tid); break;
        case 15: prep_level<32, LB_(4), 8, 5>(F4, w, sa, tid); break;
        case 16: prep_level<32, LB_(4), 8, 6>(F4, w, sa, tid); break;
        default: prep_level<32, LB_(4), 8, 7>(F4, w, sa, tid); break;
    }
}

// ---------------------------------------------------------------------------
// k_sample (R14-proven): smem = packed grids only (125184 B).
// (point,level)-per-thread-slot mapping; coalesced register stores.
// ---------------------------------------------------------------------------
#define NTHR 1024

__global__ void __launch_bounds__(NTHR, 1)
k_sample(const float* __restrict__ X, const float* __restrict__ Y,
         float* __restrict__ out, int npts) {
    extern __shared__ unsigned char smraw[];
    const int tid = threadIdx.x;

    // coalesced copy of packed grids: 7824 uint4
    {
        const uint4* src = reinterpret_cast<const uint4*>(g_G);
        uint4* dst = reinterpret_cast<uint4*>(smraw);
        for (int i = tid; i < GBT / 16; i += NTHR) dst[i] = src[i];
    }
    __syncthreads();

    const int warpid = tid >> 5;
    const int lane   = tid & 31;

    // loop-invariant per-slot state: q = (s*32+lane)/5, level consts packed
    int      qoff_[5];
    float    sx_[5];
    unsigned lr_[5];          // lbase | (rowb << 16);  asize = rowb*rowb/8
    #pragma unroll
    for (int s = 0; s < 5; s++) {
        int j = s * 32 + lane;
        int q = j / 5;
        int l = j - q * 5;
        qoff_[s] = q;
        int n2 = (l == 0) ? 16 : (l == 1) ? 24 : (l == 2) ? 40 : (l == 3) ? 36 : 64;
        unsigned lbase = (l == 0) ? 0u : (l == 1) ? 4096u : (l == 2) ? 13312u
                       : (l == 3) ? 38912u : 59648u;
        sx_[s] = (float)(n2 - 2);
        lr_[s] = lbase | ((unsigned)(n2 * 8) << 16);
    }

    float4* og = reinterpret_cast<float4*>(out);
    const int gstride = gridDim.x * NTHR;

    for (int p0 = blockIdx.x * NTHR; p0 < npts; p0 += gstride) {
        int wb = p0 + warpid * 32;          // this warp's 32-point window
        if (wb >= npts) break;
        size_t ob = (size_t)wb * 5 + lane;  // store base (float4 units)

        #pragma unroll
        for (int s = 0; s < 5; s++) {
            int p = wb + qoff_[s];
            if (p < npts) {
                float hx = __ldg(&X[p]);    // x in [0,1): h = x*(2r-2)
                float hy = __ldg(&Y[p]);

                unsigned lr    = lr_[s];
                unsigned lbase = lr & 0xFFFFu;
                unsigned rowb  = lr >> 16;
                unsigned asize = (rowb * rowb) >> 3;   // n2*n2*8
                float sx = sx_[s];

                float h = hx * sx;
                float v = hy * sx;
                float fm = floorf(h), fk = floorf(v);
                int m0 = (int)fm, k0 = (int)fk;        // in-range, no clamps
                float wx = h - fm, wy = v - fk;

                unsigned addr = lbase + (unsigned)(m0 & 1) * asize
                              + (unsigned)k0 * rowb + (unsigned)(m0 & ~1) * 8u;
                uint4 t0 = *reinterpret_cast<const uint4*>(smraw + addr);         // c00,c01
                uint4 t1 = *reinterpret_cast<const uint4*>(smraw + addr + rowb);  // c10,c11

                float2 a00 = __half22float2(*reinterpret_cast<__half2*>(&t0.x));
                float2 b00 = __half22float2(*reinterpret_cast<__half2*>(&t0.y));
                float2 a01 = __half22float2(*reinterpret_cast<__half2*>(&t0.z));
                float2 b01 = __half22float2(*reinterpret_cast<__half2*>(&t0.w));
                float2 a10 = __half22float2(*reinterpret_cast<__half2*>(&t1.x));
                float2 b10 = __half22float2(*reinterpret_cast<__half2*>(&t1.y));
                float2 a11 = __half22float2(*reinterpret_cast<__half2*>(&t1.z));
                float2 b11 = __half22float2(*reinterpret_cast<__half2*>(&t1.w));

                float wyS = wy * SCALE_DN;
                float wyB = SCALE_DN - wyS;            // (1-wy)*2^-10 exactly
                float wxb = 1.f - wx;
                float w00 = wxb * wyB;
                float w01 = wx  * wyB;
                float w10 = wxb * wyS;
                float w11 = wx  * wyS;

                float4 o;
                o.x = a00.x * w00 + a01.x * w01 + a10.x * w10 + a11.x * w11;
                o.y = a00.y * w00 + a01.y * w01 + a10.y * w10 + a11.y * w11;
                o.z = b00.x * w00 + b01.x * w01 + b10.x * w10 + b11.x * w11;
                o.w = b00.y * w00 + b01.y * w01 + b10.y * w10 + b11.y * w11;

                og[ob + s * 32] = o;        // fully coalesced STG.128
            }
        }
    }
}

// ---------------------------------------------------------------------------
extern "C" void kernel_launch(void* const* d_in, const int* in_sizes, int n_in,
                              void* d_out, int out_size) {
    const float* X = nullptr;
    const float* Yv = nullptr;
    const float* W = nullptr;
    const float* F[5] = {nullptr, nullptr, nullptr, nullptr, nullptr};
    int npts = 0;

    for (int i = 0; i < n_in; i++) {
        int s = in_sizes[i];
        const float* p = (const float*)d_in[i];
        if (s == 36)        W    = p;
        else if (s == 512)  F[0] = p;
        else if (s == 1152) F[1] = p;
        else if (s == 3200) F[2] = p;
        else if (s == 2592) F[3] = p;
        else if (s == 8192) F[4] = p;
        else {
            if (!X) { X = p; npts = s; }
            else     Yv = p;
        }
    }

    static int nsm = 0;
    static bool init_done = false;
    if (!init_done) {
        cudaFuncSetAttribute(k_sample, cudaFuncAttributeMaxDynamicSharedMemorySize, GBT);
        cudaDeviceGetAttribute(&nsm, cudaDevAttrMultiProcessorCount, 0);
        if (nsm <= 0) nsm = 148;
        init_done = true;
    }

    k_prep<<<18, 1024>>>(F[0], F[1], F[2], F[3], F[4], W);
    k_sample<<<nsm, NTHR, GBT>>>(X, Yv, (float*)d_out, npts);
}